// round 1
// baseline (speedup 1.0000x reference)
#include <cuda_runtime.h>

#define BATCH 512
#define NODES 128
#define NFEAT 256
#define KTOT  (NODES * NFEAT)      // 32768
#define KSPLIT 16
#define KSLICE (KTOT / KSPLIT)     // 2048
#define SEC    (BATCH * NFEAT)     // 131072 elements per output section

// Scratch (allocation-free rule: __device__ globals)
__device__ float g_support[BATCH * NODES * NFEAT];   // 67 MB
__device__ float g_mid[BATCH * NODES * NFEAT];       // 67 MB
__device__ float g_partial[KSPLIT * BATCH * NFEAT];  // 8.4 MB

// ---------------------------------------------------------------------------
// Generic batched GEMM  C[b] = A[b] (MxK, row-major) * B[b] (KxN, row-major)
// (+ optional bias over N).  Tile 64x64, BK=16, 256 threads, 4x4 per thread.
// grid = (N/64, M/64, batch)
// ---------------------------------------------------------------------------
__global__ __launch_bounds__(256)
void gemm_nn(const float* __restrict__ Aall, const float* __restrict__ Ball,
             const float* __restrict__ bias, float* __restrict__ Call,
             int M, int N, int K,
             long strideA, long strideB, long strideC)
{
    const long b = blockIdx.z;
    const float* A = Aall + b * strideA;
    const float* B = Ball + b * strideB;
    float*       C = Call + b * strideC;

    const int m0 = blockIdx.y * 64;
    const int n0 = blockIdx.x * 64;

    __shared__ float As[16][64];   // [k][m]
    __shared__ float Bs[16][64];   // [k][n]

    const int tid = threadIdx.x;
    const int tx = tid & 15;       // n direction
    const int ty = tid >> 4;       // m direction

    // Load mapping
    const int arow = tid >> 2;            // 0..63 : m within tile
    const int aq   = (tid & 3) * 4;       // 0,4,8,12 : k quad
    const int brow = tid >> 4;            // 0..15 : k within tile
    const int bq   = (tid & 15) * 4;      // 0..60 : n quad

    float acc[4][4] = {};

    for (int k0 = 0; k0 < K; k0 += 16) {
        float4 av = *(const float4*)&A[(long)(m0 + arow) * K + k0 + aq];
        float4 bv = *(const float4*)&B[(long)(k0 + brow) * N + n0 + bq];
        __syncthreads();
        As[aq + 0][arow] = av.x;
        As[aq + 1][arow] = av.y;
        As[aq + 2][arow] = av.z;
        As[aq + 3][arow] = av.w;
        *(float4*)&Bs[brow][bq] = bv;
        __syncthreads();

        #pragma unroll
        for (int k = 0; k < 16; k++) {
            float ar[4];
            #pragma unroll
            for (int i = 0; i < 4; i++) ar[i] = As[k][ty * 4 + i];
            float4 b4 = *(const float4*)&Bs[k][tx * 4];
            float br[4] = {b4.x, b4.y, b4.z, b4.w};
            #pragma unroll
            for (int i = 0; i < 4; i++)
                #pragma unroll
                for (int j = 0; j < 4; j++)
                    acc[i][j] += ar[i] * br[j];
        }
    }

    #pragma unroll
    for (int i = 0; i < 4; i++) {
        const int m = m0 + ty * 4 + i;
        #pragma unroll
        for (int j = 0; j < 4; j++) {
            const int n = n0 + tx * 4 + j;
            float v = acc[i][j];
            if (bias) v += bias[n];
            C[(long)m * N + n] = v;
        }
    }
}

// ---------------------------------------------------------------------------
// FC layer, split-K:  P[s][m][n] = sum_{k in slice s} mid[m][k] * fcw[n][k]
// mid viewed as [512][32768], fcw [256][32768] (both K-contiguous -> GEMM-NT)
// grid = (256/64, 512/64, KSPLIT) = (4, 8, 16)
// ---------------------------------------------------------------------------
__global__ __launch_bounds__(256)
void gemm_nt_splitk(const float* __restrict__ A, const float* __restrict__ Bt,
                    float* __restrict__ P)
{
    const int split = blockIdx.z;
    const int m0 = blockIdx.y * 64;
    const int n0 = blockIdx.x * 64;
    const long kbase = (long)split * KSLICE;

    __shared__ float As[16][64];   // [k][m]
    __shared__ float Bs[16][64];   // [k][n]

    const int tid = threadIdx.x;
    const int tx = tid & 15;
    const int ty = tid >> 4;

    const int row = tid >> 2;         // 0..63
    const int q   = (tid & 3) * 4;    // k quad

    float acc[4][4] = {};

    for (int k0 = 0; k0 < KSLICE; k0 += 16) {
        float4 av = *(const float4*)&A [(long)(m0 + row) * KTOT + kbase + k0 + q];
        float4 bv = *(const float4*)&Bt[(long)(n0 + row) * KTOT + kbase + k0 + q];
        __syncthreads();
        As[q + 0][row] = av.x;  Bs[q + 0][row] = bv.x;
        As[q + 1][row] = av.y;  Bs[q + 1][row] = bv.y;
        As[q + 2][row] = av.z;  Bs[q + 2][row] = bv.z;
        As[q + 3][row] = av.w;  Bs[q + 3][row] = bv.w;
        __syncthreads();

        #pragma unroll
        for (int k = 0; k < 16; k++) {
            float ar[4], br[4];
            #pragma unroll
            for (int i = 0; i < 4; i++) ar[i] = As[k][ty * 4 + i];
            #pragma unroll
            for (int j = 0; j < 4; j++) br[j] = Bs[k][tx * 4 + j];
            #pragma unroll
            for (int i = 0; i < 4; i++)
                #pragma unroll
                for (int j = 0; j < 4; j++)
                    acc[i][j] += ar[i] * br[j];
        }
    }

    float* Pd = P + (long)split * SEC;
    #pragma unroll
    for (int i = 0; i < 4; i++) {
        const int m = m0 + ty * 4 + i;
        #pragma unroll
        for (int j = 0; j < 4; j++) {
            const int n = n0 + tx * 4 + j;
            Pd[(long)m * NFEAT + n] = acc[i][j];
        }
    }
}

// ---------------------------------------------------------------------------
// Deterministic reduction over split-K partials + fc_b, plus the two copies:
// out[0:SEC]      = output
// out[SEC:2SEC]   = x[:,0,:]
// out[2SEC:3SEC]  = output
// ---------------------------------------------------------------------------
__global__ __launch_bounds__(256)
void finalize(const float* __restrict__ P, const float* __restrict__ fc_b,
              const float* __restrict__ x, float* __restrict__ out)
{
    const int idx = blockIdx.x * blockDim.x + threadIdx.x;
    if (idx >= SEC) return;
    const int b = idx >> 8;    // / NFEAT
    const int f = idx & 255;   // % NFEAT
    float v = fc_b[f];
    #pragma unroll
    for (int s = 0; s < KSPLIT; s++)
        v += P[(long)s * SEC + idx];
    out[idx]           = v;
    out[2 * SEC + idx] = v;
    out[SEC + idx]     = x[(long)b * KTOT + f];   // x[b,0,f]
}

// ---------------------------------------------------------------------------
extern "C" void kernel_launch(void* const* d_in, const int* in_sizes, int n_in,
                              void* d_out, int out_size)
{
    const float* x     = (const float*)d_in[0];   // [512,128,256]
    const float* adj   = (const float*)d_in[1];   // [512,128,128]
    const float* gcn_w = (const float*)d_in[2];   // [256,256]
    const float* gcn_b = (const float*)d_in[3];   // [256]
    const float* fc_w  = (const float*)d_in[4];   // [256,32768]
    const float* fc_b  = (const float*)d_in[5];   // [256]
    float* out = (float*)d_out;

    float* support;  cudaGetSymbolAddress((void**)&support, g_support);
    float* mid;      cudaGetSymbolAddress((void**)&mid,     g_mid);
    float* partial;  cudaGetSymbolAddress((void**)&partial, g_partial);

    // 1) support[b] = x[b] @ gcn_w           (M=128, N=256, K=256)
    {
        dim3 grid(NFEAT / 64, NODES / 64, BATCH);
        gemm_nn<<<grid, 256>>>(x, gcn_w, nullptr, support,
                               NODES, NFEAT, NFEAT,
                               (long)NODES * NFEAT, 0L, (long)NODES * NFEAT);
    }
    // 2) mid[b] = adj[b] @ support[b] + gcn_b (M=128, N=256, K=128)
    {
        dim3 grid(NFEAT / 64, NODES / 64, BATCH);
        gemm_nn<<<grid, 256>>>(adj, support, gcn_b, mid,
                               NODES, NFEAT, NODES,
                               (long)NODES * NODES, (long)NODES * NFEAT,
                               (long)NODES * NFEAT);
    }
    // 3) split-K FC:  partial[s] = mid_flat @ fc_w^T  (slice s)
    {
        dim3 grid(NFEAT / 64, BATCH / 64, KSPLIT);
        gemm_nt_splitk<<<grid, 256>>>(mid, fc_w, partial);
    }
    // 4) reduce + bias + copies
    finalize<<<SEC / 256, 256>>>(partial, fc_b, x, out);
}

// round 3
// speedup vs baseline: 1.8802x; 1.8802x over previous
#include <cuda_runtime.h>
#include <cuda_bf16.h>
#include <cstdint>

#define BATCH 512
#define NODES 128
#define NFEAT 256
#define KTOT  32768          // NODES*NFEAT
#define SPLITS 32
#define KSLICE 1024          // KTOT/SPLITS
#define SEC   (BATCH*NFEAT)  // 131072

// ---------------------------------------------------------------------------
// Scratch (__device__ globals; allocation is forbidden)
// ---------------------------------------------------------------------------
__device__ __nv_bfloat16 g_gwT_hi[NFEAT * NFEAT];                  // [g][f]
__device__ __nv_bfloat16 g_gwT_lo[NFEAT * NFEAT];
__device__ __nv_bfloat16 g_supT_hi[(size_t)BATCH * NFEAT * NODES]; // [b][g][node]
__device__ __nv_bfloat16 g_supT_lo[(size_t)BATCH * NFEAT * NODES];
__device__ __nv_bfloat16 g_mid_hi[(size_t)BATCH * NODES * NFEAT];  // [b][node][g]
__device__ __nv_bfloat16 g_mid_lo[(size_t)BATCH * NODES * NFEAT];
__device__ float         g_partial[(size_t)SPLITS * BATCH * NFEAT];

// ---------------------------------------------------------------------------
#define SW128(o) ((o) ^ (((o) >> 3) & 0x70))

__device__ __forceinline__ uint32_t smem_u32(const void* p) {
    uint32_t a;
    asm("{ .reg .u64 t; cvta.to.shared.u64 t, %1; cvt.u32.u64 %0, t; }"
        : "=r"(a) : "l"(p));
    return a;
}

__device__ __forceinline__ void split1(float v, __nv_bfloat16& h, __nv_bfloat16& l) {
    h = __float2bfloat16(v);
    l = __float2bfloat16(v - __bfloat162float(h));
}
__device__ __forceinline__ uint32_t pack2(__nv_bfloat16 a, __nv_bfloat16 b) {
    __nv_bfloat162 t = __halves2bfloat162(a, b);
    return *reinterpret_cast<uint32_t*>(&t);
}
__device__ __forceinline__ void store_split4(char* hi, char* lo, uint32_t boff, float4 v) {
    uint32_t so = SW128(boff);
    __nv_bfloat16 h0, h1, h2, h3, l0, l1, l2, l3;
    split1(v.x, h0, l0); split1(v.y, h1, l1);
    split1(v.z, h2, l2); split1(v.w, h3, l3);
    uint2 hu, lu;
    hu.x = pack2(h0, h1); hu.y = pack2(h2, h3);
    lu.x = pack2(l0, l1); lu.y = pack2(l2, l3);
    *(uint2*)(hi + so) = hu;
    *(uint2*)(lo + so) = lu;
}

// ---------------------------------------------------------------------------
// warp-MMA primitives (base PTX: valid at compute_103)
// ---------------------------------------------------------------------------
__device__ __forceinline__ void ldsm_x4(uint32_t addr, uint32_t* r) {
    asm volatile("ldmatrix.sync.aligned.m8n8.x4.shared.b16 {%0,%1,%2,%3}, [%4];"
        : "=r"(r[0]), "=r"(r[1]), "=r"(r[2]), "=r"(r[3]) : "r"(addr));
}
__device__ __forceinline__ void ldsm_x2(uint32_t addr, uint32_t* r) {
    asm volatile("ldmatrix.sync.aligned.m8n8.x2.shared.b16 {%0,%1}, [%2];"
        : "=r"(r[0]), "=r"(r[1]) : "r"(addr));
}
__device__ __forceinline__ void mma_bf16(float* c, const uint32_t* a, const uint32_t* b) {
    asm volatile(
        "mma.sync.aligned.m16n8k16.row.col.f32.bf16.bf16.f32 "
        "{%0,%1,%2,%3}, {%4,%5,%6,%7}, {%8,%9}, {%0,%1,%2,%3};"
        : "+f"(c[0]), "+f"(c[1]), "+f"(c[2]), "+f"(c[3])
        : "r"(a[0]), "r"(a[1]), "r"(a[2]), "r"(a[3]), "r"(b[0]), "r"(b[1]));
}

// load A fragments for this warp's 4 m-tiles from a [128][64]bf16 SW128 tile
__device__ __forceinline__ void load_afrags(uint32_t tbase, int m0w, int kb,
                                            int lane, uint32_t* a) {
    const int kpart = ((lane >> 4) << 4);   // 0 or 16 bytes
    #pragma unroll
    for (int i = 0; i < 4; i++) {
        int row = m0w + 16 * i + (lane & 15);
        ldsm_x4(tbase + SW128(row * 128 + kb + kpart), a + 4 * i);
    }
}
// load B fragments for this warp's 4 n-tiles
__device__ __forceinline__ void load_bfrags(uint32_t tbase, int n0w, int kb,
                                            int lane, uint32_t* b) {
    const int kpart = (((lane >> 3) & 1) << 4);  // 0 or 16 bytes
    #pragma unroll
    for (int j = 0; j < 4; j++) {
        int row = n0w + 8 * j + (lane & 7);
        ldsm_x2(tbase + SW128(row * 128 + kb + kpart), b + 2 * j);
    }
}
__device__ __forceinline__ void mma_all(float* acc, const uint32_t* a, const uint32_t* b) {
    #pragma unroll
    for (int i = 0; i < 4; i++)
        #pragma unroll
        for (int j = 0; j < 4; j++)
            mma_bf16(acc + (i * 4 + j) * 4, a + 4 * i, b + 2 * j);
}

// ---------------------------------------------------------------------------
// SMEM: (1024 align pad) + Ahi 16K | Alo 16K | Bhi 16K | Blo 16K
// ---------------------------------------------------------------------------
#define OFF_AHI 0
#define OFF_ALO 16384
#define OFF_BHI 32768
#define OFF_BLO 49152
#define SMEM_BYTES (65536 + 1024)

// ---------------------------------------------------------------------------
// Unified warp-MMA GEMM: C[128,128] = A[128,K] * B[128,K]^T  (k-tile 64)
// MODE 1: A = gwT (bf16 pair), B = x_b (fp32)    -> supT[g][node] (bf16 pair)
// MODE 2: A = adj_b (fp32), B = supT_b (bf16)    -> mid[node][g] + gcn_b (bf16 pair)
// MODE 3: A = mid (bf16 pair), B = fc_w (fp32)   -> partial (fp32)
// ---------------------------------------------------------------------------
template <int MODE>
__global__ void __launch_bounds__(256, 2)
gemm_w(const float* __restrict__ Af, long sAf,
       const __nv_bfloat16* __restrict__ Ahi, const __nv_bfloat16* __restrict__ Alo, long sAb,
       const float* __restrict__ Bf, long sBf,
       const __nv_bfloat16* __restrict__ Bhi, const __nv_bfloat16* __restrict__ Blo, long sBb,
       const float* __restrict__ bias,
       float* __restrict__ outF, __nv_bfloat16* __restrict__ outHi,
       __nv_bfloat16* __restrict__ outLo, int nkt)
{
    extern __shared__ char smraw[];
    char* sm = (char*)(((uintptr_t)smraw + 1023) & ~(uintptr_t)1023);
    const uint32_t sb = smem_u32(sm);

    const int tid  = threadIdx.x;
    const int lane = tid & 31;
    const int w    = tid >> 5;
    const int m0w  = (w >> 2) * 64;
    const int n0w  = (w & 3) * 32;

    int ldc = 0, coloff = 0;
    if constexpr (MODE == 1) {
        long b = blockIdx.x, mh = blockIdx.y;
        Ahi += mh * 128 * NFEAT;  Alo += mh * 128 * NFEAT;
        Bf  += b * (long)(NODES * NFEAT);
        outHi += b * (long)(NFEAT * NODES) + mh * 128 * NODES;
        outLo += b * (long)(NFEAT * NODES) + mh * 128 * NODES;
        ldc = NODES;
    } else if constexpr (MODE == 2) {
        long b = blockIdx.x, nh = blockIdx.y;
        Af  += b * (long)(NODES * NODES);
        Bhi += b * (long)(NFEAT * NODES) + nh * 128 * NODES;
        Blo += b * (long)(NFEAT * NODES) + nh * 128 * NODES;
        outHi += b * (long)(NODES * NFEAT);
        outLo += b * (long)(NODES * NFEAT);
        bias += nh * 128;
        ldc = NFEAT; coloff = (int)nh * 128;
    } else {
        long split = blockIdx.x, mb = blockIdx.y, nh = blockIdx.z;
        Ahi += (mb * 128) * (long)KTOT + split * KSLICE;
        Alo += (mb * 128) * (long)KTOT + split * KSLICE;
        Bf  += (nh * 128) * (long)KTOT + split * KSLICE;
        outF += split * (long)SEC + (mb * 128) * (long)NFEAT + nh * 128;
        ldc = NFEAT;
    }

    float acc[64];
    #pragma unroll
    for (int i = 0; i < 64; i++) acc[i] = 0.f;

    for (int kt = 0; kt < nkt; kt++) {
        const int k0 = kt * 64;
        __syncthreads();
        // ---- stage A tile [128][64] ----
        if constexpr (MODE == 2) {
            #pragma unroll
            for (int it = 0; it < 8; it++) {
                int idx = tid + it * 256;
                int row = idx >> 4, c4 = idx & 15;
                float4 v = *(const float4*)(Af + (long)row * sAf + k0 + c4 * 4);
                store_split4(sm + OFF_AHI, sm + OFF_ALO, row * 128 + c4 * 8, v);
            }
        } else {
            #pragma unroll
            for (int it = 0; it < 4; it++) {
                int idx = tid + it * 256;
                int row = idx >> 3, c = idx & 7;
                uint32_t so = SW128(row * 128 + c * 16);
                *(uint4*)(sm + OFF_AHI + so) = *(const uint4*)(Ahi + (long)row * sAb + k0 + c * 8);
                *(uint4*)(sm + OFF_ALO + so) = *(const uint4*)(Alo + (long)row * sAb + k0 + c * 8);
            }
        }
        // ---- stage B tile [128][64] ----
        if constexpr (MODE == 2) {
            #pragma unroll
            for (int it = 0; it < 4; it++) {
                int idx = tid + it * 256;
                int row = idx >> 3, c = idx & 7;
                uint32_t so = SW128(row * 128 + c * 16);
                *(uint4*)(sm + OFF_BHI + so) = *(const uint4*)(Bhi + (long)row * sBb + k0 + c * 8);
                *(uint4*)(sm + OFF_BLO + so) = *(const uint4*)(Blo + (long)row * sBb + k0 + c * 8);
            }
        } else {
            #pragma unroll
            for (int it = 0; it < 8; it++) {
                int idx = tid + it * 256;
                int row = idx >> 4, c4 = idx & 15;
                float4 v = *(const float4*)(Bf + (long)row * sBf + k0 + c4 * 4);
                store_split4(sm + OFF_BHI, sm + OFF_BLO, row * 128 + c4 * 8, v);
            }
        }
        __syncthreads();

        // ---- compute: 4 k16 steps, 3-term bf16 emulation ----
        #pragma unroll
        for (int ks = 0; ks < 4; ks++) {
            const int kb = ks * 32;
            uint32_t a[16], b[8];
            load_afrags(sb + OFF_AHI, m0w, kb, lane, a);
            load_bfrags(sb + OFF_BHI, n0w, kb, lane, b);
            mma_all(acc, a, b);                       // hi*hi
            load_bfrags(sb + OFF_BLO, n0w, kb, lane, b);
            mma_all(acc, a, b);                       // hi*lo
            load_afrags(sb + OFF_ALO, m0w, kb, lane, a);
            load_bfrags(sb + OFF_BHI, n0w, kb, lane, b);
            mma_all(acc, a, b);                       // lo*hi
        }
    }

    // ---- epilogue ----
    #pragma unroll
    for (int i = 0; i < 4; i++) {
        #pragma unroll
        for (int j = 0; j < 4; j++) {
            const float* c = acc + (i * 4 + j) * 4;
            int r0 = m0w + 16 * i + (lane >> 2);
            int c0 = n0w + 8 * j + 2 * (lane & 3);
            if constexpr (MODE == 3) {
                *(float2*)&outF[(long)r0 * ldc + c0]       = make_float2(c[0], c[1]);
                *(float2*)&outF[(long)(r0 + 8) * ldc + c0] = make_float2(c[2], c[3]);
            } else {
                float v0 = c[0], v1 = c[1], v2 = c[2], v3 = c[3];
                if constexpr (MODE == 2) {
                    float b0 = __ldg(&bias[c0]), b1 = __ldg(&bias[c0 + 1]);
                    v0 += b0; v1 += b1; v2 += b0; v3 += b1;
                }
                __nv_bfloat16 h0, l0, h1, l1;
                split1(v0, h0, l0); split1(v1, h1, l1);
                long o0 = (long)r0 * ldc + coloff + c0;
                *(uint32_t*)&outHi[o0] = pack2(h0, h1);
                *(uint32_t*)&outLo[o0] = pack2(l0, l1);
                split1(v2, h0, l0); split1(v3, h1, l1);
                long o1 = (long)(r0 + 8) * ldc + coloff + c0;
                *(uint32_t*)&outHi[o1] = pack2(h0, h1);
                *(uint32_t*)&outLo[o1] = pack2(l0, l1);
            }
        }
    }
}

// ---------------------------------------------------------------------------
// prep: gwT[g][f] = gcn_w[f][g], split into bf16 hi/lo
// ---------------------------------------------------------------------------
__global__ void __launch_bounds__(256)
prep_w(const float* __restrict__ wsrc, __nv_bfloat16* __restrict__ hi,
       __nv_bfloat16* __restrict__ lo)
{
    int g = blockIdx.x, f = threadIdx.x;
    float v = wsrc[(long)f * NFEAT + g];
    __nv_bfloat16 h, l; split1(v, h, l);
    hi[(long)g * NFEAT + f] = h;
    lo[(long)g * NFEAT + f] = l;
}

// ---------------------------------------------------------------------------
// finalize: reduce split-K partials + fc_b, write 3 output sections
// ---------------------------------------------------------------------------
__global__ void __launch_bounds__(256)
finalize(const float* __restrict__ P, const float* __restrict__ fc_b,
         const float* __restrict__ x, float* __restrict__ out)
{
    const int idx = blockIdx.x * blockDim.x + threadIdx.x;
    if (idx >= SEC) return;
    const int b = idx >> 8;
    const int f = idx & 255;
    float v = fc_b[f];
    #pragma unroll
    for (int s = 0; s < SPLITS; s++)
        v += P[(long)s * SEC + idx];
    out[idx]           = v;
    out[2 * SEC + idx] = v;
    out[SEC + idx]     = x[(long)b * KTOT + f];   // x[b,0,f]
}

// ---------------------------------------------------------------------------
extern "C" void kernel_launch(void* const* d_in, const int* in_sizes, int n_in,
                              void* d_out, int out_size)
{
    const float* x     = (const float*)d_in[0];   // [512,128,256]
    const float* adj   = (const float*)d_in[1];   // [512,128,128]
    const float* gcn_w = (const float*)d_in[2];   // [256,256]
    const float* gcn_b = (const float*)d_in[3];   // [256]
    const float* fc_w  = (const float*)d_in[4];   // [256,32768]
    const float* fc_b  = (const float*)d_in[5];   // [256]
    float* out = (float*)d_out;

    __nv_bfloat16 *gwT_hi, *gwT_lo, *supT_hi, *supT_lo, *mid_hi, *mid_lo;
    float* partial;
    cudaGetSymbolAddress((void**)&gwT_hi,  g_gwT_hi);
    cudaGetSymbolAddress((void**)&gwT_lo,  g_gwT_lo);
    cudaGetSymbolAddress((void**)&supT_hi, g_supT_hi);
    cudaGetSymbolAddress((void**)&supT_lo, g_supT_lo);
    cudaGetSymbolAddress((void**)&mid_hi,  g_mid_hi);
    cudaGetSymbolAddress((void**)&mid_lo,  g_mid_lo);
    cudaGetSymbolAddress((void**)&partial, g_partial);

    cudaFuncSetAttribute(gemm_w<1>, cudaFuncAttributeMaxDynamicSharedMemorySize, SMEM_BYTES);
    cudaFuncSetAttribute(gemm_w<2>, cudaFuncAttributeMaxDynamicSharedMemorySize, SMEM_BYTES);
    cudaFuncSetAttribute(gemm_w<3>, cudaFuncAttributeMaxDynamicSharedMemorySize, SMEM_BYTES);

    // 0) transpose + split gcn_w -> gwT[g][f]
    prep_w<<<NFEAT, NFEAT>>>(gcn_w, gwT_hi, gwT_lo);

    // 1) supT[b][g][node] : C[m=g][n=node] = sum_f gwT[g][f] * x_b[node][f]
    {
        dim3 grid(BATCH, 2);   // (batch, m-half)
        gemm_w<1><<<grid, 256, SMEM_BYTES>>>(
            nullptr, 0, gwT_hi, gwT_lo, NFEAT,
            x, NFEAT, nullptr, nullptr, 0,
            nullptr, nullptr, supT_hi, supT_lo, 4);
    }
    // 2) mid[b][node][g] : C[m=node][n=g] = sum_k adj_b[node][k] * supT_b[g][k] + gcn_b[g]
    {
        dim3 grid(BATCH, 2);   // (batch, n-half)
        gemm_w<2><<<grid, 256, SMEM_BYTES>>>(
            adj, NODES, nullptr, nullptr, 0,
            nullptr, 0, supT_hi, supT_lo, NODES,
            gcn_b, nullptr, mid_hi, mid_lo, 2);
    }
    // 3) partial[s][m][n] = sum_{k in slice} mid[m][k] * fc_w[n][k]
    {
        dim3 grid(SPLITS, BATCH / 128, 2);   // (split, m-block, n-half)
        gemm_w<3><<<grid, 256, SMEM_BYTES>>>(
            nullptr, 0, mid_hi, mid_lo, KTOT,
            fc_w, KTOT, nullptr, nullptr, 0,
            nullptr, partial, nullptr, nullptr, KSLICE / 64);
    }
    // 4) reduce + bias + output sections
    finalize<<<SEC / 256, 256>>>(partial, fc_b, x, out);
}

// round 4
// speedup vs baseline: 2.6350x; 1.4014x over previous
#include <cuda_runtime.h>
#include <cuda_bf16.h>
#include <cstdint>

#define BATCH 512
#define NODES 128
#define NFEAT 256
#define KTOT  32768          // NODES*NFEAT
#define SPLITS 16
#define KSLICE 2048          // KTOT/SPLITS
#define SEC   (BATCH*NFEAT)  // 131072

// ---------------------------------------------------------------------------
// Scratch (__device__ globals; allocation is forbidden)
// ---------------------------------------------------------------------------
__device__ __nv_bfloat16 g_gwT_hi[NFEAT * NFEAT];                   // [g][f]
__device__ __nv_bfloat16 g_gwT_lo[NFEAT * NFEAT];
__device__ __nv_bfloat16 g_x_hi[(size_t)BATCH * NODES * NFEAT];     // [b][node][f]
__device__ __nv_bfloat16 g_x_lo[(size_t)BATCH * NODES * NFEAT];
__device__ __nv_bfloat16 g_adj_hi[(size_t)BATCH * NODES * NODES];   // [b][n][m]
__device__ __nv_bfloat16 g_adj_lo[(size_t)BATCH * NODES * NODES];
__device__ __nv_bfloat16 g_fcw_hi[(size_t)NFEAT * KTOT];            // [o][k]
__device__ __nv_bfloat16 g_fcw_lo[(size_t)NFEAT * KTOT];
__device__ __nv_bfloat16 g_supT_hi[(size_t)BATCH * NFEAT * NODES];  // [b][g][node]
__device__ __nv_bfloat16 g_supT_lo[(size_t)BATCH * NFEAT * NODES];
__device__ __nv_bfloat16 g_mid_hi[(size_t)BATCH * NODES * NFEAT];   // [b][node][g]
__device__ __nv_bfloat16 g_mid_lo[(size_t)BATCH * NODES * NFEAT];
__device__ float         g_partial[(size_t)SPLITS * BATCH * NFEAT];

// ---------------------------------------------------------------------------
#define SW128(o) ((o) ^ (((o) >> 3) & 0x70))

__device__ __forceinline__ uint32_t smem_u32(const void* p) {
    uint32_t a;
    asm("{ .reg .u64 t; cvta.to.shared.u64 t, %1; cvt.u32.u64 %0, t; }"
        : "=r"(a) : "l"(p));
    return a;
}
__device__ __forceinline__ void split1(float v, __nv_bfloat16& h, __nv_bfloat16& l) {
    h = __float2bfloat16(v);
    l = __float2bfloat16(v - __bfloat162float(h));
}
__device__ __forceinline__ uint32_t pack2(__nv_bfloat16 a, __nv_bfloat16 b) {
    __nv_bfloat162 t = __halves2bfloat162(a, b);
    return *reinterpret_cast<uint32_t*>(&t);
}

// ---------------------------------------------------------------------------
// cp.async (base PTX, sm_80+)
// ---------------------------------------------------------------------------
__device__ __forceinline__ void cpa16(uint32_t s, const void* g) {
    asm volatile("cp.async.cg.shared.global [%0], [%1], 16;" :: "r"(s), "l"(g));
}
#define CP_COMMIT()  asm volatile("cp.async.commit_group;" ::: "memory")
#define CP_WAIT1()   asm volatile("cp.async.wait_group 1;" ::: "memory")
#define CP_WAIT0()   asm volatile("cp.async.wait_group 0;" ::: "memory")

// ---------------------------------------------------------------------------
// warp-MMA primitives (base PTX)
// ---------------------------------------------------------------------------
__device__ __forceinline__ void ldsm_x4(uint32_t addr, uint32_t* r) {
    asm volatile("ldmatrix.sync.aligned.m8n8.x4.shared.b16 {%0,%1,%2,%3}, [%4];"
        : "=r"(r[0]), "=r"(r[1]), "=r"(r[2]), "=r"(r[3]) : "r"(addr));
}
__device__ __forceinline__ void ldsm_x2(uint32_t addr, uint32_t* r) {
    asm volatile("ldmatrix.sync.aligned.m8n8.x2.shared.b16 {%0,%1}, [%2];"
        : "=r"(r[0]), "=r"(r[1]) : "r"(addr));
}
__device__ __forceinline__ void mma_bf16(float* c, const uint32_t* a, const uint32_t* b) {
    asm volatile(
        "mma.sync.aligned.m16n8k16.row.col.f32.bf16.bf16.f32 "
        "{%0,%1,%2,%3}, {%4,%5,%6,%7}, {%8,%9}, {%0,%1,%2,%3};"
        : "+f"(c[0]), "+f"(c[1]), "+f"(c[2]), "+f"(c[3])
        : "r"(a[0]), "r"(a[1]), "r"(a[2]), "r"(a[3]), "r"(b[0]), "r"(b[1]));
}
__device__ __forceinline__ void load_afrags(uint32_t tbase, int m0w, int kb,
                                            int lane, uint32_t* a) {
    const int kpart = ((lane >> 4) << 4);
    #pragma unroll
    for (int i = 0; i < 4; i++) {
        int row = m0w + 16 * i + (lane & 15);
        ldsm_x4(tbase + SW128(row * 128 + kb + kpart), a + 4 * i);
    }
}
__device__ __forceinline__ void load_bfrags(uint32_t tbase, int n0w, int kb,
                                            int lane, uint32_t* b) {
    const int kpart = (((lane >> 3) & 1) << 4);
    #pragma unroll
    for (int j = 0; j < 4; j++) {
        int row = n0w + 8 * j + (lane & 7);
        ldsm_x2(tbase + SW128(row * 128 + kb + kpart), b + 2 * j);
    }
}
__device__ __forceinline__ void mma_all(float* acc, const uint32_t* a, const uint32_t* b) {
    #pragma unroll
    for (int i = 0; i < 4; i++)
        #pragma unroll
        for (int j = 0; j < 4; j++)
            mma_bf16(acc + (i * 4 + j) * 4, a + 4 * i, b + 2 * j);
}

// ---------------------------------------------------------------------------
// SMEM layout: 2 stages x (Ahi 16K | Alo 16K | Bhi 16K | Blo 16K)
// ---------------------------------------------------------------------------
#define OFF_ALO 16384
#define OFF_BHI 32768
#define OFF_BLO 49152
#define STAGE_STRIDE 65536
#define SMEM_BYTES (2 * STAGE_STRIDE + 1024)

// ---------------------------------------------------------------------------
// Uniform pipelined GEMM: C[128,128] = A[128,K] * B[128,K]^T, all bf16 pairs
// MODE 1: A=gwT, B=x_b       -> supT pairs
// MODE 2: A=adj_b, B=supT_b  -> mid pairs + gcn_b
// MODE 3: A=mid, B=fcw       -> partial fp32
// ---------------------------------------------------------------------------
template <int MODE>
__global__ void __launch_bounds__(256, 1)
gemm_p(const __nv_bfloat16* __restrict__ Ahi, const __nv_bfloat16* __restrict__ Alo, long sA,
       const __nv_bfloat16* __restrict__ Bhi, const __nv_bfloat16* __restrict__ Blo, long sB,
       const float* __restrict__ bias,
       float* __restrict__ outF, __nv_bfloat16* __restrict__ outHi,
       __nv_bfloat16* __restrict__ outLo, int nkt)
{
    extern __shared__ char smraw[];
    char* sm = (char*)(((uintptr_t)smraw + 1023) & ~(uintptr_t)1023);
    const uint32_t sb = smem_u32(sm);

    const int tid  = threadIdx.x;
    const int lane = tid & 31;
    const int w    = tid >> 5;
    const int m0w  = (w >> 2) * 64;
    const int n0w  = (w & 3) * 32;

    int ldc = 0, coloff = 0;
    if constexpr (MODE == 1) {
        long b = blockIdx.x, mh = blockIdx.y;
        Ahi += mh * 128 * NFEAT;  Alo += mh * 128 * NFEAT;
        Bhi += b * (long)(NODES * NFEAT);  Blo += b * (long)(NODES * NFEAT);
        outHi += b * (long)(NFEAT * NODES) + mh * 128 * NODES;
        outLo += b * (long)(NFEAT * NODES) + mh * 128 * NODES;
        ldc = NODES;
    } else if constexpr (MODE == 2) {
        long b = blockIdx.x, nh = blockIdx.y;
        Ahi += b * (long)(NODES * NODES);  Alo += b * (long)(NODES * NODES);
        Bhi += b * (long)(NFEAT * NODES) + nh * 128 * NODES;
        Blo += b * (long)(NFEAT * NODES) + nh * 128 * NODES;
        outHi += b * (long)(NODES * NFEAT);
        outLo += b * (long)(NODES * NFEAT);
        bias += nh * 128;
        ldc = NFEAT; coloff = (int)nh * 128;
    } else {
        long split = blockIdx.x, mb = blockIdx.y, nh = blockIdx.z;
        Ahi += (mb * 128) * (long)KTOT + split * KSLICE;
        Alo += (mb * 128) * (long)KTOT + split * KSLICE;
        Bhi += (nh * 128) * (long)KTOT + split * KSLICE;
        Blo += (nh * 128) * (long)KTOT + split * KSLICE;
        outF += split * (long)SEC + (mb * 128) * (long)NFEAT + nh * 128;
        ldc = NFEAT;
    }

    // stage loader: 16 x cp.async(16B) per thread
    auto stage_load = [&](int stage, int kt) {
        const uint32_t base = sb + stage * STAGE_STRIDE;
        const int k0 = kt * 64;
        #pragma unroll
        for (int it = 0; it < 4; it++) {
            int idx = tid + it * 256;
            int row = idx >> 3, c = idx & 7;
            uint32_t so = SW128(row * 128 + c * 16);
            long ga = (long)row * sA + k0 + c * 8;
            long gb = (long)row * sB + k0 + c * 8;
            cpa16(base + so,           Ahi + ga);
            cpa16(base + OFF_ALO + so, Alo + ga);
            cpa16(base + OFF_BHI + so, Bhi + gb);
            cpa16(base + OFF_BLO + so, Blo + gb);
        }
    };

    float acc[64];
    #pragma unroll
    for (int i = 0; i < 64; i++) acc[i] = 0.f;

    // prologue: fill both stages
    stage_load(0, 0); CP_COMMIT();
    if (nkt > 1) stage_load(1, 1);
    CP_COMMIT();

    for (int kt = 0; kt < nkt; kt++) {
        const int st = kt & 1;
        if (kt + 1 < nkt) CP_WAIT1(); else CP_WAIT0();
        __syncthreads();

        const uint32_t base = sb + st * STAGE_STRIDE;
        #pragma unroll
        for (int ks = 0; ks < 4; ks++) {
            const int kb = ks * 32;
            uint32_t ah[16], al[16], bh[8], bl[8];
            load_afrags(base,           m0w, kb, lane, ah);
            load_bfrags(base + OFF_BHI, n0w, kb, lane, bh);
            load_bfrags(base + OFF_BLO, n0w, kb, lane, bl);
            load_afrags(base + OFF_ALO, m0w, kb, lane, al);
            mma_all(acc, ah, bh);   // hi*hi
            mma_all(acc, ah, bl);   // hi*lo
            mma_all(acc, al, bh);   // lo*hi
        }
        __syncthreads();
        if (kt + 2 < nkt) stage_load(st, kt + 2);
        CP_COMMIT();
    }

    // ---- epilogue ----
    #pragma unroll
    for (int i = 0; i < 4; i++) {
        #pragma unroll
        for (int j = 0; j < 4; j++) {
            const float* c = acc + (i * 4 + j) * 4;
            int r0 = m0w + 16 * i + (lane >> 2);
            int c0 = n0w + 8 * j + 2 * (lane & 3);
            if constexpr (MODE == 3) {
                *(float2*)&outF[(long)r0 * ldc + c0]       = make_float2(c[0], c[1]);
                *(float2*)&outF[(long)(r0 + 8) * ldc + c0] = make_float2(c[2], c[3]);
            } else {
                float v0 = c[0], v1 = c[1], v2 = c[2], v3 = c[3];
                if constexpr (MODE == 2) {
                    float b0 = __ldg(&bias[c0]), b1 = __ldg(&bias[c0 + 1]);
                    v0 += b0; v1 += b1; v2 += b0; v3 += b1;
                }
                __nv_bfloat16 h0, l0, h1, l1;
                split1(v0, h0, l0); split1(v1, h1, l1);
                long o0 = (long)r0 * ldc + coloff + c0;
                *(uint32_t*)&outHi[o0] = pack2(h0, h1);
                *(uint32_t*)&outLo[o0] = pack2(l0, l1);
                split1(v2, h0, l0); split1(v3, h1, l1);
                long o1 = (long)(r0 + 8) * ldc + coloff + c0;
                *(uint32_t*)&outHi[o1] = pack2(h0, h1);
                *(uint32_t*)&outLo[o1] = pack2(l0, l1);
            }
        }
    }
}

// ---------------------------------------------------------------------------
// prep: elementwise fp32 -> bf16 hi/lo pair split (vectorized x4)
// ---------------------------------------------------------------------------
__global__ void __launch_bounds__(256)
split_arr(const float* __restrict__ src, __nv_bfloat16* __restrict__ hi,
          __nv_bfloat16* __restrict__ lo, long n4)
{
    long i = (long)blockIdx.x * 256 + threadIdx.x;
    if (i >= n4) return;
    float4 v = ((const float4*)src)[i];
    __nv_bfloat16 h0, h1, h2, h3, l0, l1, l2, l3;
    split1(v.x, h0, l0); split1(v.y, h1, l1);
    split1(v.z, h2, l2); split1(v.w, h3, l3);
    ((uint2*)hi)[i] = make_uint2(pack2(h0, h1), pack2(h2, h3));
    ((uint2*)lo)[i] = make_uint2(pack2(l0, l1), pack2(l2, l3));
}

// prep: gwT[g][f] = gcn_w[f][g], split
__global__ void __launch_bounds__(256)
prep_w(const float* __restrict__ wsrc, __nv_bfloat16* __restrict__ hi,
       __nv_bfloat16* __restrict__ lo)
{
    int g = blockIdx.x, f = threadIdx.x;
    float v = wsrc[(long)f * NFEAT + g];
    __nv_bfloat16 h, l; split1(v, h, l);
    hi[(long)g * NFEAT + f] = h;
    lo[(long)g * NFEAT + f] = l;
}

// ---------------------------------------------------------------------------
// finalize: reduce split-K partials + fc_b, write 3 output sections
// ---------------------------------------------------------------------------
__global__ void __launch_bounds__(256)
finalize(const float* __restrict__ P, const float* __restrict__ fc_b,
         const float* __restrict__ x, float* __restrict__ out)
{
    const int idx = blockIdx.x * blockDim.x + threadIdx.x;
    if (idx >= SEC) return;
    const int b = idx >> 8;
    const int f = idx & 255;
    float v = fc_b[f];
    #pragma unroll
    for (int s = 0; s < SPLITS; s++)
        v += P[(long)s * SEC + idx];
    out[idx]           = v;
    out[2 * SEC + idx] = v;
    out[SEC + idx]     = x[(long)b * KTOT + f];   // x[b,0,f]
}

// ---------------------------------------------------------------------------
extern "C" void kernel_launch(void* const* d_in, const int* in_sizes, int n_in,
                              void* d_out, int out_size)
{
    const float* x     = (const float*)d_in[0];
    const float* adj   = (const float*)d_in[1];
    const float* gcn_w = (const float*)d_in[2];
    const float* gcn_b = (const float*)d_in[3];
    const float* fc_w  = (const float*)d_in[4];
    const float* fc_b  = (const float*)d_in[5];
    float* out = (float*)d_out;

    __nv_bfloat16 *gwT_hi, *gwT_lo, *x_hi, *x_lo, *adj_hi, *adj_lo;
    __nv_bfloat16 *fcw_hi, *fcw_lo, *supT_hi, *supT_lo, *mid_hi, *mid_lo;
    float* partial;
    cudaGetSymbolAddress((void**)&gwT_hi,  g_gwT_hi);
    cudaGetSymbolAddress((void**)&gwT_lo,  g_gwT_lo);
    cudaGetSymbolAddress((void**)&x_hi,    g_x_hi);
    cudaGetSymbolAddress((void**)&x_lo,    g_x_lo);
    cudaGetSymbolAddress((void**)&adj_hi,  g_adj_hi);
    cudaGetSymbolAddress((void**)&adj_lo,  g_adj_lo);
    cudaGetSymbolAddress((void**)&fcw_hi,  g_fcw_hi);
    cudaGetSymbolAddress((void**)&fcw_lo,  g_fcw_lo);
    cudaGetSymbolAddress((void**)&supT_hi, g_supT_hi);
    cudaGetSymbolAddress((void**)&supT_lo, g_supT_lo);
    cudaGetSymbolAddress((void**)&mid_hi,  g_mid_hi);
    cudaGetSymbolAddress((void**)&mid_lo,  g_mid_lo);
    cudaGetSymbolAddress((void**)&partial, g_partial);

    cudaFuncSetAttribute(gemm_p<1>, cudaFuncAttributeMaxDynamicSharedMemorySize, SMEM_BYTES);
    cudaFuncSetAttribute(gemm_p<2>, cudaFuncAttributeMaxDynamicSharedMemorySize, SMEM_BYTES);
    cudaFuncSetAttribute(gemm_p<3>, cudaFuncAttributeMaxDynamicSharedMemorySize, SMEM_BYTES);

    // 0) preps
    prep_w<<<NFEAT, NFEAT>>>(gcn_w, gwT_hi, gwT_lo);
    {
        long n4 = (long)BATCH * NODES * NFEAT / 4;        // x
        split_arr<<<(unsigned)((n4 + 255) / 256), 256>>>(x, x_hi, x_lo, n4);
    }
    {
        long n4 = (long)BATCH * NODES * NODES / 4;        // adj
        split_arr<<<(unsigned)((n4 + 255) / 256), 256>>>(adj, adj_hi, adj_lo, n4);
    }
    {
        long n4 = (long)NFEAT * KTOT / 4;                 // fc_w
        split_arr<<<(unsigned)((n4 + 255) / 256), 256>>>(fc_w, fcw_hi, fcw_lo, n4);
    }

    // 1) supT[b][g][node] = sum_f gwT[g][f] * x_b[node][f]
    {
        dim3 grid(BATCH, 2);
        gemm_p<1><<<grid, 256, SMEM_BYTES>>>(
            gwT_hi, gwT_lo, NFEAT, x_hi, x_lo, NFEAT,
            nullptr, nullptr, supT_hi, supT_lo, 4);
    }
    // 2) mid[b][node][g] = sum_k adj_b[node][k] * supT_b[g][k] + gcn_b[g]
    {
        dim3 grid(BATCH, 2);
        gemm_p<2><<<grid, 256, SMEM_BYTES>>>(
            adj_hi, adj_lo, NODES, supT_hi, supT_lo, NODES,
            gcn_b, nullptr, mid_hi, mid_lo, 2);
    }
    // 3) partial[s][m][n] = sum_{k in slice} mid[m][k] * fcw[n][k]
    {
        dim3 grid(SPLITS, BATCH / 128, 2);
        gemm_p<3><<<grid, 256, SMEM_BYTES>>>(
            mid_hi, mid_lo, KTOT, fcw_hi, fcw_lo, KTOT,
            nullptr, partial, nullptr, nullptr, KSLICE / 64);
    }
    // 4) reduce + bias + output sections
    finalize<<<SEC / 256, 256>>>(partial, fc_b, x, out);
}

// round 5
// speedup vs baseline: 2.6353x; 1.0001x over previous
#include <cuda_runtime.h>
#include <cuda_bf16.h>
#include <cstdint>

#define BATCH 512
#define NODES 128
#define NFEAT 256
#define KTOT  32768          // NODES*NFEAT
#define SPLITS 16
#define KSLICE 2048          // KTOT/SPLITS
#define SEC   (BATCH*NFEAT)  // 131072

// ---------------------------------------------------------------------------
// Scratch (__device__ globals; allocation is forbidden)
// ---------------------------------------------------------------------------
__device__ __nv_bfloat16 g_gwT_hi[NFEAT * NFEAT];                   // [g][f]
__device__ __nv_bfloat16 g_gwT_lo[NFEAT * NFEAT];
__device__ __nv_bfloat16 g_x_hi[(size_t)BATCH * NODES * NFEAT];     // [b][node][f]
__device__ __nv_bfloat16 g_x_lo[(size_t)BATCH * NODES * NFEAT];
__device__ __nv_bfloat16 g_adj_hi[(size_t)BATCH * NODES * NODES];   // [b][n][m]
__device__ __nv_bfloat16 g_adj_lo[(size_t)BATCH * NODES * NODES];
__device__ __nv_bfloat16 g_fcw_hi[(size_t)NFEAT * KTOT];            // [o][k]
__device__ __nv_bfloat16 g_fcw_lo[(size_t)NFEAT * KTOT];
__device__ __nv_bfloat16 g_supT_hi[(size_t)BATCH * NFEAT * NODES];  // [b][g][node]
__device__ __nv_bfloat16 g_supT_lo[(size_t)BATCH * NFEAT * NODES];
__device__ __nv_bfloat16 g_mid_hi[(size_t)BATCH * NODES * NFEAT];   // [b][node][g]
__device__ __nv_bfloat16 g_mid_lo[(size_t)BATCH * NODES * NFEAT];
__device__ float         g_partial[(size_t)SPLITS * BATCH * NFEAT];

// ---------------------------------------------------------------------------
#define SW128(o) ((o) ^ (((o) >> 3) & 0x70))

__device__ __forceinline__ uint32_t smem_u32(const void* p) {
    uint32_t a;
    asm("{ .reg .u64 t; cvta.to.shared.u64 t, %1; cvt.u32.u64 %0, t; }"
        : "=r"(a) : "l"(p));
    return a;
}
__device__ __forceinline__ void split1(float v, __nv_bfloat16& h, __nv_bfloat16& l) {
    h = __float2bfloat16(v);
    l = __float2bfloat16(v - __bfloat162float(h));
}
__device__ __forceinline__ uint32_t pack2(__nv_bfloat16 a, __nv_bfloat16 b) {
    __nv_bfloat162 t = __halves2bfloat162(a, b);
    return *reinterpret_cast<uint32_t*>(&t);
}

// ---------------------------------------------------------------------------
// cp.async (base PTX, sm_80+)
// ---------------------------------------------------------------------------
__device__ __forceinline__ void cpa16(uint32_t s, const void* g) {
    asm volatile("cp.async.cg.shared.global [%0], [%1], 16;" :: "r"(s), "l"(g));
}
#define CP_COMMIT()  asm volatile("cp.async.commit_group;" ::: "memory")
#define CP_WAIT1()   asm volatile("cp.async.wait_group 1;" ::: "memory")
#define CP_WAIT0()   asm volatile("cp.async.wait_group 0;" ::: "memory")

// ---------------------------------------------------------------------------
// warp-MMA primitives (base PTX)
// ---------------------------------------------------------------------------
__device__ __forceinline__ void ldsm_x4(uint32_t addr, uint32_t* r) {
    asm volatile("ldmatrix.sync.aligned.m8n8.x4.shared.b16 {%0,%1,%2,%3}, [%4];"
        : "=r"(r[0]), "=r"(r[1]), "=r"(r[2]), "=r"(r[3]) : "r"(addr));
}
__device__ __forceinline__ void ldsm_x2(uint32_t addr, uint32_t* r) {
    asm volatile("ldmatrix.sync.aligned.m8n8.x2.shared.b16 {%0,%1}, [%2];"
        : "=r"(r[0]), "=r"(r[1]) : "r"(addr));
}
__device__ __forceinline__ void mma_bf16(float* c, const uint32_t* a, const uint32_t* b) {
    asm volatile(
        "mma.sync.aligned.m16n8k16.row.col.f32.bf16.bf16.f32 "
        "{%0,%1,%2,%3}, {%4,%5,%6,%7}, {%8,%9}, {%0,%1,%2,%3};"
        : "+f"(c[0]), "+f"(c[1]), "+f"(c[2]), "+f"(c[3])
        : "r"(a[0]), "r"(a[1]), "r"(a[2]), "r"(a[3]), "r"(b[0]), "r"(b[1]));
}
__device__ __forceinline__ void load_afrags(uint32_t tbase, int m0w, int kb,
                                            int lane, uint32_t* a) {
    const int kpart = ((lane >> 4) << 4);
    #pragma unroll
    for (int i = 0; i < 4; i++) {
        int row = m0w + 16 * i + (lane & 15);
        ldsm_x4(tbase + SW128(row * 128 + kb + kpart), a + 4 * i);
    }
}
__device__ __forceinline__ void load_bfrags(uint32_t tbase, int n0w, int kb,
                                            int lane, uint32_t* b) {
    const int kpart = (((lane >> 3) & 1) << 4);
    #pragma unroll
    for (int j = 0; j < 4; j++) {
        int row = n0w + 8 * j + (lane & 7);
        ldsm_x2(tbase + SW128(row * 128 + kb + kpart), b + 2 * j);
    }
}
__device__ __forceinline__ void mma_all(float* acc, const uint32_t* a, const uint32_t* b) {
    #pragma unroll
    for (int i = 0; i < 4; i++)
        #pragma unroll
        for (int j = 0; j < 4; j++)
            mma_bf16(acc + (i * 4 + j) * 4, a + 4 * i, b + 2 * j);
}

// ---------------------------------------------------------------------------
// SMEM layout: 3 stages x (Ahi 16K | Alo 16K | Bhi 16K | Blo 16K)
// ---------------------------------------------------------------------------
#define OFF_ALO 16384
#define OFF_BHI 32768
#define OFF_BLO 49152
#define STAGE_STRIDE 65536
#define NSTAGE 3
#define SMEM_BYTES (NSTAGE * STAGE_STRIDE + 1024)

// ---------------------------------------------------------------------------
// Uniform pipelined GEMM: C[128,128] = A[128,K] * B[128,K]^T, all bf16 pairs
// MODE 1: A=gwT, B=x_b       -> supT pairs
// MODE 2: A=adj_b, B=supT_b  -> mid pairs + gcn_b
// MODE 3: A=mid, B=fcw       -> partial fp32
// ---------------------------------------------------------------------------
template <int MODE>
__global__ void __launch_bounds__(256, 1)
gemm_p(const __nv_bfloat16* __restrict__ Ahi, const __nv_bfloat16* __restrict__ Alo, long sA,
       const __nv_bfloat16* __restrict__ Bhi, const __nv_bfloat16* __restrict__ Blo, long sB,
       const float* __restrict__ bias,
       float* __restrict__ outF, __nv_bfloat16* __restrict__ outHi,
       __nv_bfloat16* __restrict__ outLo, int nkt)
{
    extern __shared__ char smraw[];
    char* sm = (char*)(((uintptr_t)smraw + 1023) & ~(uintptr_t)1023);
    const uint32_t sb = smem_u32(sm);

    const int tid  = threadIdx.x;
    const int lane = tid & 31;
    const int w    = tid >> 5;
    const int m0w  = (w >> 2) * 64;
    const int n0w  = (w & 3) * 32;

    int ldc = 0, coloff = 0;
    if constexpr (MODE == 1) {
        long b = blockIdx.x, mh = blockIdx.y;
        Ahi += mh * 128 * NFEAT;  Alo += mh * 128 * NFEAT;
        Bhi += b * (long)(NODES * NFEAT);  Blo += b * (long)(NODES * NFEAT);
        outHi += b * (long)(NFEAT * NODES) + mh * 128 * NODES;
        outLo += b * (long)(NFEAT * NODES) + mh * 128 * NODES;
        ldc = NODES;
    } else if constexpr (MODE == 2) {
        long b = blockIdx.x, nh = blockIdx.y;
        Ahi += b * (long)(NODES * NODES);  Alo += b * (long)(NODES * NODES);
        Bhi += b * (long)(NFEAT * NODES) + nh * 128 * NODES;
        Blo += b * (long)(NFEAT * NODES) + nh * 128 * NODES;
        outHi += b * (long)(NODES * NFEAT);
        outLo += b * (long)(NODES * NFEAT);
        bias += nh * 128;
        ldc = NFEAT; coloff = (int)nh * 128;
    } else {
        long split = blockIdx.x, mb = blockIdx.y, nh = blockIdx.z;
        Ahi += (mb * 128) * (long)KTOT + split * KSLICE;
        Alo += (mb * 128) * (long)KTOT + split * KSLICE;
        Bhi += (nh * 128) * (long)KTOT + split * KSLICE;
        Blo += (nh * 128) * (long)KTOT + split * KSLICE;
        outF += split * (long)SEC + (mb * 128) * (long)NFEAT + nh * 128;
        ldc = NFEAT;
    }

    // stage loader: 16 x cp.async(16B) per thread
    auto stage_load = [&](int stage, int kt) {
        const uint32_t base = sb + stage * STAGE_STRIDE;
        const int k0 = kt * 64;
        #pragma unroll
        for (int it = 0; it < 4; it++) {
            int idx = tid + it * 256;
            int row = idx >> 3, c = idx & 7;
            uint32_t so = SW128(row * 128 + c * 16);
            long ga = (long)row * sA + k0 + c * 8;
            long gb = (long)row * sB + k0 + c * 8;
            cpa16(base + so,           Ahi + ga);
            cpa16(base + OFF_ALO + so, Alo + ga);
            cpa16(base + OFF_BHI + so, Bhi + gb);
            cpa16(base + OFF_BLO + so, Blo + gb);
        }
    };

    float acc[64];
    #pragma unroll
    for (int i = 0; i < 64; i++) acc[i] = 0.f;

    // prologue: fill stages 0 and 1
    stage_load(0, 0); CP_COMMIT();
    if (nkt > 1) stage_load(1, 1);
    CP_COMMIT();

    int st = 0;
    for (int kt = 0; kt < nkt; kt++) {
        // stage kt becomes ready when at most 1 newer group is outstanding
        if (kt + 1 < nkt) CP_WAIT1(); else CP_WAIT0();
        __syncthreads();
        // issue next-next load into the slot freed at iteration kt-1,
        // BEFORE compute so DRAM fetch overlaps the MMA burst
        if (kt + 2 < nkt) {
            int st2 = st + 2; if (st2 >= NSTAGE) st2 -= NSTAGE;
            stage_load(st2, kt + 2);
            CP_COMMIT();
        }

        const uint32_t base = sb + st * STAGE_STRIDE;
        #pragma unroll
        for (int ks = 0; ks < 4; ks++) {
            const int kb = ks * 32;
            uint32_t ah[16], al[16], bh[8], bl[8];
            load_afrags(base,           m0w, kb, lane, ah);
            load_bfrags(base + OFF_BHI, n0w, kb, lane, bh);
            load_bfrags(base + OFF_BLO, n0w, kb, lane, bl);
            load_afrags(base + OFF_ALO, m0w, kb, lane, al);
            mma_all(acc, ah, bh);   // hi*hi
            mma_all(acc, ah, bl);   // hi*lo
            mma_all(acc, al, bh);   // lo*hi
        }
        if (++st == NSTAGE) st = 0;
    }

    // ---- epilogue ----
    #pragma unroll
    for (int i = 0; i < 4; i++) {
        #pragma unroll
        for (int j = 0; j < 4; j++) {
            const float* c = acc + (i * 4 + j) * 4;
            int r0 = m0w + 16 * i + (lane >> 2);
            int c0 = n0w + 8 * j + 2 * (lane & 3);
            if constexpr (MODE == 3) {
                *(float2*)&outF[(long)r0 * ldc + c0]       = make_float2(c[0], c[1]);
                *(float2*)&outF[(long)(r0 + 8) * ldc + c0] = make_float2(c[2], c[3]);
            } else {
                float v0 = c[0], v1 = c[1], v2 = c[2], v3 = c[3];
                if constexpr (MODE == 2) {
                    float b0 = __ldg(&bias[c0]), b1 = __ldg(&bias[c0 + 1]);
                    v0 += b0; v1 += b1; v2 += b0; v3 += b1;
                }
                __nv_bfloat16 h0, l0, h1, l1;
                split1(v0, h0, l0); split1(v1, h1, l1);
                long o0 = (long)r0 * ldc + coloff + c0;
                *(uint32_t*)&outHi[o0] = pack2(h0, h1);
                *(uint32_t*)&outLo[o0] = pack2(l0, l1);
                split1(v2, h0, l0); split1(v3, h1, l1);
                long o1 = (long)(r0 + 8) * ldc + coloff + c0;
                *(uint32_t*)&outHi[o1] = pack2(h0, h1);
                *(uint32_t*)&outLo[o1] = pack2(l0, l1);
            }
        }
    }
}

// ---------------------------------------------------------------------------
// prep: elementwise fp32 -> bf16 hi/lo pair split (vectorized x4)
// ---------------------------------------------------------------------------
__global__ void __launch_bounds__(256)
split_arr(const float* __restrict__ src, __nv_bfloat16* __restrict__ hi,
          __nv_bfloat16* __restrict__ lo, long n4)
{
    long i = (long)blockIdx.x * 256 + threadIdx.x;
    if (i >= n4) return;
    float4 v = ((const float4*)src)[i];
    __nv_bfloat16 h0, h1, h2, h3, l0, l1, l2, l3;
    split1(v.x, h0, l0); split1(v.y, h1, l1);
    split1(v.z, h2, l2); split1(v.w, h3, l3);
    ((uint2*)hi)[i] = make_uint2(pack2(h0, h1), pack2(h2, h3));
    ((uint2*)lo)[i] = make_uint2(pack2(l0, l1), pack2(l2, l3));
}

// prep: gwT[g][f] = gcn_w[f][g], split
__global__ void __launch_bounds__(256)
prep_w(const float* __restrict__ wsrc, __nv_bfloat16* __restrict__ hi,
       __nv_bfloat16* __restrict__ lo)
{
    int g = blockIdx.x, f = threadIdx.x;
    float v = wsrc[(long)f * NFEAT + g];
    __nv_bfloat16 h, l; split1(v, h, l);
    hi[(long)g * NFEAT + f] = h;
    lo[(long)g * NFEAT + f] = l;
}

// ---------------------------------------------------------------------------
// finalize: reduce split-K partials + fc_b, write 3 output sections
// ---------------------------------------------------------------------------
__global__ void __launch_bounds__(256)
finalize(const float* __restrict__ P, const float* __restrict__ fc_b,
         const float* __restrict__ x, float* __restrict__ out)
{
    const int idx = blockIdx.x * blockDim.x + threadIdx.x;
    if (idx >= SEC) return;
    const int b = idx >> 8;
    const int f = idx & 255;
    float v = fc_b[f];
    #pragma unroll
    for (int s = 0; s < SPLITS; s++)
        v += P[(long)s * SEC + idx];
    out[idx]           = v;
    out[2 * SEC + idx] = v;
    out[SEC + idx]     = x[(long)b * KTOT + f];   // x[b,0,f]
}

// ---------------------------------------------------------------------------
extern "C" void kernel_launch(void* const* d_in, const int* in_sizes, int n_in,
                              void* d_out, int out_size)
{
    const float* x     = (const float*)d_in[0];
    const float* adj   = (const float*)d_in[1];
    const float* gcn_w = (const float*)d_in[2];
    const float* gcn_b = (const float*)d_in[3];
    const float* fc_w  = (const float*)d_in[4];
    const float* fc_b  = (const float*)d_in[5];
    float* out = (float*)d_out;

    __nv_bfloat16 *gwT_hi, *gwT_lo, *x_hi, *x_lo, *adj_hi, *adj_lo;
    __nv_bfloat16 *fcw_hi, *fcw_lo, *supT_hi, *supT_lo, *mid_hi, *mid_lo;
    float* partial;
    cudaGetSymbolAddress((void**)&gwT_hi,  g_gwT_hi);
    cudaGetSymbolAddress((void**)&gwT_lo,  g_gwT_lo);
    cudaGetSymbolAddress((void**)&x_hi,    g_x_hi);
    cudaGetSymbolAddress((void**)&x_lo,    g_x_lo);
    cudaGetSymbolAddress((void**)&adj_hi,  g_adj_hi);
    cudaGetSymbolAddress((void**)&adj_lo,  g_adj_lo);
    cudaGetSymbolAddress((void**)&fcw_hi,  g_fcw_hi);
    cudaGetSymbolAddress((void**)&fcw_lo,  g_fcw_lo);
    cudaGetSymbolAddress((void**)&supT_hi, g_supT_hi);
    cudaGetSymbolAddress((void**)&supT_lo, g_supT_lo);
    cudaGetSymbolAddress((void**)&mid_hi,  g_mid_hi);
    cudaGetSymbolAddress((void**)&mid_lo,  g_mid_lo);
    cudaGetSymbolAddress((void**)&partial, g_partial);

    cudaFuncSetAttribute(gemm_p<1>, cudaFuncAttributeMaxDynamicSharedMemorySize, SMEM_BYTES);
    cudaFuncSetAttribute(gemm_p<2>, cudaFuncAttributeMaxDynamicSharedMemorySize, SMEM_BYTES);
    cudaFuncSetAttribute(gemm_p<3>, cudaFuncAttributeMaxDynamicSharedMemorySize, SMEM_BYTES);

    // 0) preps
    prep_w<<<NFEAT, NFEAT>>>(gcn_w, gwT_hi, gwT_lo);
    {
        long n4 = (long)BATCH * NODES * NFEAT / 4;        // x
        split_arr<<<(unsigned)((n4 + 255) / 256), 256>>>(x, x_hi, x_lo, n4);
    }
    {
        long n4 = (long)BATCH * NODES * NODES / 4;        // adj
        split_arr<<<(unsigned)((n4 + 255) / 256), 256>>>(adj, adj_hi, adj_lo, n4);
    }
    {
        long n4 = (long)NFEAT * KTOT / 4;                 // fc_w
        split_arr<<<(unsigned)((n4 + 255) / 256), 256>>>(fc_w, fcw_hi, fcw_lo, n4);
    }

    // 1) supT[b][g][node] = sum_f gwT[g][f] * x_b[node][f]
    {
        dim3 grid(BATCH, 2);
        gemm_p<1><<<grid, 256, SMEM_BYTES>>>(
            gwT_hi, gwT_lo, NFEAT, x_hi, x_lo, NFEAT,
            nullptr, nullptr, supT_hi, supT_lo, 4);
    }
    // 2) mid[b][node][g] = sum_k adj_b[node][k] * supT_b[g][k] + gcn_b[g]
    {
        dim3 grid(BATCH, 2);
        gemm_p<2><<<grid, 256, SMEM_BYTES>>>(
            adj_hi, adj_lo, NODES, supT_hi, supT_lo, NODES,
            gcn_b, nullptr, mid_hi, mid_lo, 2);
    }
    // 3) partial[s][m][n] = sum_{k in slice} mid[m][k] * fcw[n][k]
    {
        dim3 grid(SPLITS, BATCH / 128, 2);
        gemm_p<3><<<grid, 256, SMEM_BYTES>>>(
            mid_hi, mid_lo, KTOT, fcw_hi, fcw_lo, KTOT,
            nullptr, partial, nullptr, nullptr, KSLICE / 64);
    }
    // 4) reduce + bias + output sections
    finalize<<<SEC / 256, 256>>>(partial, fc_b, x, out);
}